// round 15
// baseline (speedup 1.0000x reference)
#include <cuda_runtime.h>
#include <stdint.h>

// Problem constants: B=24, D=128, N=2048, M=2048
#define TOTAL_OUT 25165824u  // 24*512*2048

// ---------------- scratch (device globals; no allocations allowed) ----------------
__device__ float g_S  [(size_t)24 * 2048 * 2048];   // logits S[b][n][m]
__device__ float g_A  [(size_t)24 * 128 * 2048];    // A[b][d][n]
__device__ float g_V  [(size_t)24 * 128 * 2048];    // V[b][d][m] = C @ S2
__device__ float g_Bt [(size_t)24 * 128 * 2048];    // Bt[b][d][k] = V @ S1^T
__device__ float g_sq [24 * 2048];
__device__ float g_sc [24 * 2048];
__device__ float g_rmax[24 * 2048];                 // per-row max of S
__device__ float g_rinv[24 * 2048];                 // 1 / rowsum(exp(S - rmax))
__device__ float g_cmax[24 * 2048];                 // per-col max of S

// ---------------- float atomic max (mixed-sign safe, order-independent) ----------------
__device__ __forceinline__ void atomicMaxF(float* a, float v)
{
    if (v >= 0.f) atomicMax((int*)a, __float_as_int(v));
    else          atomicMin((unsigned int*)a, __float_as_uint(v));
}

// ---------------- init: rmax/cmax = -inf ----------------
__global__ __launch_bounds__(256) void init_kernel()
{
    const int i = blockIdx.x * 256 + threadIdx.x;   // i < 49152
    g_rmax[i] = __int_as_float(0xff800000);
    g_cmax[i] = __int_as_float(0xff800000);
}

// ---------------- sq / sc ----------------
__global__ __launch_bounds__(256) void sqsc_kernel(const float* __restrict__ C,
                                                   const float* __restrict__ Q,
                                                   const float* __restrict__ W)
{
    const int b = blockIdx.y;
    const int which = blockIdx.z;     // 0 -> sq (Wq . Q), 1 -> sc (Wc . C)
    const float* X = which ? C : Q;
    const float* w = W + b * 384 + (which ? 128 : 0);
    __shared__ float ws[128];
    if (threadIdx.x < 128) ws[threadIdx.x] = w[threadIdx.x];
    __syncthreads();
    const int m = blockIdx.x * 256 + threadIdx.x;
    const float* Xp = X + (size_t)b * 128 * 2048 + m;
    float acc = 0.f;
    #pragma unroll 8
    for (int d = 0; d < 128; d++)
        acc += ws[d] * Xp[(size_t)d * 2048];
    (which ? g_sc : g_sq)[b * 2048 + m] = acc;
}

// ---------------- GEMM1: S[n][m] = sum_d (C[d][n]*Wm[d]) * Q[d][m] + sc[n] + sq[m] -----
// Epilogue also reduces per-row and per-column tile maxes -> atomicMaxF into g_rmax/g_cmax.
__global__ __launch_bounds__(256) void gemm1_kernel(const float* __restrict__ C,
                                                    const float* __restrict__ Q,
                                                    const float* __restrict__ W)
{
    const int b  = blockIdx.z;
    const int n0 = blockIdx.y * 128;
    const int m0 = blockIdx.x * 128;
    const float* Cb = C + (size_t)b * 128 * 2048;
    const float* Qb = Q + (size_t)b * 128 * 2048;
    const float* Wm = W + b * 384 + 256;

    __shared__ float As[16][128];
    __shared__ float Bs[16][128];
    __shared__ float cms[16][136];

    const int tid = threadIdx.x;
    const int tx = tid & 15;          // m dir
    const int ty = tid >> 4;          // n dir
    const int lk = tid >> 4;          // load row in k-tile (0..15)
    const int lc = (tid & 15) * 8;    // load col (0..120)

    float acc[8][8];
    #pragma unroll
    for (int i = 0; i < 8; i++)
        #pragma unroll
        for (int j = 0; j < 8; j++) acc[i][j] = 0.f;

    for (int d0 = 0; d0 < 128; d0 += 16) {
        const float w = Wm[d0 + lk];
        const float4 c0 = *(const float4*)(Cb + (size_t)(d0 + lk) * 2048 + n0 + lc);
        const float4 c1 = *(const float4*)(Cb + (size_t)(d0 + lk) * 2048 + n0 + lc + 4);
        const float4 q0 = *(const float4*)(Qb + (size_t)(d0 + lk) * 2048 + m0 + lc);
        const float4 q1 = *(const float4*)(Qb + (size_t)(d0 + lk) * 2048 + m0 + lc + 4);
        if (d0) __syncthreads();
        *(float4*)&As[lk][lc]     = make_float4(c0.x * w, c0.y * w, c0.z * w, c0.w * w);
        *(float4*)&As[lk][lc + 4] = make_float4(c1.x * w, c1.y * w, c1.z * w, c1.w * w);
        *(float4*)&Bs[lk][lc]     = q0;
        *(float4*)&Bs[lk][lc + 4] = q1;
        __syncthreads();
        #pragma unroll
        for (int k = 0; k < 16; k++) {
            float a[8], bb[8];
            *(float4*)&a[0]  = *(const float4*)&As[k][ty * 8];
            *(float4*)&a[4]  = *(const float4*)&As[k][ty * 8 + 4];
            *(float4*)&bb[0] = *(const float4*)&Bs[k][tx * 8];
            *(float4*)&bb[4] = *(const float4*)&Bs[k][tx * 8 + 4];
            #pragma unroll
            for (int i = 0; i < 8; i++)
                #pragma unroll
                for (int j = 0; j < 8; j++)
                    acc[i][j] += a[i] * bb[j];
        }
    }

    const float* scp = g_sc + b * 2048 + n0 + ty * 8;
    const float* sqp = g_sq + b * 2048 + m0 + tx * 8;
    float sqv[8];
    #pragma unroll
    for (int j = 0; j < 8; j++) sqv[j] = sqp[j];

    float colm[8];
    #pragma unroll
    for (int j = 0; j < 8; j++) colm[j] = -1e30f;

    #pragma unroll
    for (int i = 0; i < 8; i++) {
        const float scv = scp[i];
        float v[8];
        float rowm = -1e30f;
        #pragma unroll
        for (int j = 0; j < 8; j++) {
            v[j] = acc[i][j] + scv + sqv[j];
            rowm = fmaxf(rowm, v[j]);
            colm[j] = fmaxf(colm[j], v[j]);
        }
        float* dst = g_S + ((size_t)b * 2048 + n0 + ty * 8 + i) * 2048 + m0 + tx * 8;
        *(float4*)dst       = make_float4(v[0], v[1], v[2], v[3]);
        *(float4*)(dst + 4) = make_float4(v[4], v[5], v[6], v[7]);
        // reduce row max over the 16 tx lanes (same half-warp)
        #pragma unroll
        for (int o = 1; o < 16; o <<= 1)
            rowm = fmaxf(rowm, __shfl_xor_sync(0xffffffffu, rowm, o));
        if (tx == 0) atomicMaxF(&g_rmax[b * 2048 + n0 + ty * 8 + i], rowm);
    }
    // column maxes: reduce over the 16 ty groups via shared
    #pragma unroll
    for (int j = 0; j < 8; j++) cms[ty][tx * 8 + j] = colm[j];
    __syncthreads();
    if (tid < 128) {
        float m = -1e30f;
        #pragma unroll
        for (int g = 0; g < 16; g++) m = fmaxf(m, cms[g][tid]);
        atomicMaxF(&g_cmax[b * 2048 + m0 + tid], m);
    }
}

// ---------------- NT GEMM: Out[b][d][j] = rinv[j] * sum_k X[b][d][k] * exp(S[j][k]-rmax[j])
// MODE 0: X = Q,   Out = A;  computes rowsum in-block, writes g_rinv.
// MODE 1: X = g_V, Out = Bt; reads g_rinv.
template<int MODE>
__global__ __launch_bounds__(256) void gemm_nt_kernel(const float* __restrict__ Xin)
{
    const int b  = blockIdx.y;
    const int j0 = blockIdx.x * 128;
    const float* X   = (MODE == 0) ? Xin : g_V;
    float* Out       = (MODE == 0) ? g_A : g_Bt;

    const float* Xb  = X + (size_t)b * 128 * 2048;
    const float* Sb  = g_S + (size_t)b * 2048 * 2048;

    __shared__ float Xs[16][132];
    __shared__ float Ss[16][132];
    __shared__ float rsum[128];

    const int tid = threadIdx.x;
    const int tx = tid & 15;
    const int ty = tid >> 4;
    const int r  = tid >> 1;           // 0..127  (row j0+r)
    const int kb = (tid & 1) * 8;      // 0 or 8

    float acc[8][8];
    #pragma unroll
    for (int i = 0; i < 8; i++)
        #pragma unroll
        for (int j = 0; j < 8; j++) acc[i][j] = 0.f;

    const float rm = g_rmax[b * 2048 + j0 + r];
    float racc = 0.f;

    for (int k0 = 0; k0 < 2048; k0 += 16) {
        float xr[8], sr[8];
        *(float4*)&xr[0] = *(const float4*)(Xb + (size_t)r * 2048 + k0 + kb);
        *(float4*)&xr[4] = *(const float4*)(Xb + (size_t)r * 2048 + k0 + kb + 4);
        *(float4*)&sr[0] = *(const float4*)(Sb + (size_t)(j0 + r) * 2048 + k0 + kb);
        *(float4*)&sr[4] = *(const float4*)(Sb + (size_t)(j0 + r) * 2048 + k0 + kb + 4);
        #pragma unroll
        for (int i = 0; i < 8; i++) {
            sr[i] = __expf(sr[i] - rm);      // in (0,1], never overflows/underflows row-wise
            if (MODE == 0) racc += sr[i];
        }
        if (k0) __syncthreads();
        #pragma unroll
        for (int i = 0; i < 8; i++) { Xs[kb + i][r] = xr[i]; Ss[kb + i][r] = sr[i]; }
        __syncthreads();
        #pragma unroll
        for (int k = 0; k < 16; k++) {
            float a[8], bb[8];
            *(float4*)&a[0]  = *(const float4*)&Xs[k][ty * 8];
            *(float4*)&a[4]  = *(const float4*)&Xs[k][ty * 8 + 4];
            *(float4*)&bb[0] = *(const float4*)&Ss[k][tx * 8];
            *(float4*)&bb[4] = *(const float4*)&Ss[k][tx * 8 + 4];
            #pragma unroll
            for (int i = 0; i < 8; i++)
                #pragma unroll
                for (int j = 0; j < 8; j++)
                    acc[i][j] += a[i] * bb[j];
        }
    }

    // rinv for this block's 128 j-columns (rowsum >= 1, always safe)
    if (MODE == 0) {
        racc += __shfl_xor_sync(0xffffffffu, racc, 1);  // merge kb=0 / kb=8 halves
        if ((tid & 1) == 0) rsum[r] = 1.f / racc;
        __syncthreads();
        if (tid < 128) g_rinv[b * 2048 + j0 + tid] = rsum[tid];
    } else {
        if (tid < 128) rsum[tid] = g_rinv[b * 2048 + j0 + tid];
        __syncthreads();
    }

    float ri[8];
    #pragma unroll
    for (int j = 0; j < 8; j++) ri[j] = rsum[tx * 8 + j];

    #pragma unroll
    for (int i = 0; i < 8; i++) {
        float* dst = Out + ((size_t)b * 128 + ty * 8 + i) * 2048 + j0 + tx * 8;
        *(float4*)dst       = make_float4(acc[i][0] * ri[0], acc[i][1] * ri[1],
                                          acc[i][2] * ri[2], acc[i][3] * ri[3]);
        *(float4*)(dst + 4) = make_float4(acc[i][4] * ri[4], acc[i][5] * ri[5],
                                          acc[i][6] * ri[6], acc[i][7] * ri[7]);
    }
}

// ---------------- NN GEMM: V[b][d][m] = cinv[m] * sum_n C[b][d][n] * exp(S[n][m]-cmax[m])
// colsum computed in-block (>= 1, always safe).
__global__ __launch_bounds__(256) void gemm_nn_kernel(const float* __restrict__ Cin)
{
    const int b  = blockIdx.y;
    const int m0 = blockIdx.x * 128;
    const float* Cb = Cin + (size_t)b * 128 * 2048;
    const float* Pb = g_S + (size_t)b * 2048 * 2048;
    const float* cm = g_cmax + b * 2048;

    __shared__ float Cs[16][132];
    __shared__ float Ss[16][132];
    __shared__ float csum[16][136];
    __shared__ float cinvs[128];

    const int tid = threadIdx.x;
    const int tx = tid & 15;
    const int ty = tid >> 4;
    const int rA  = tid >> 1;          // d row for C tile
    const int kbA = (tid & 1) * 8;     // n offset in tile
    const int kS  = tid >> 4;          // n row for S tile (0..15)
    const int cS  = (tid & 15) * 8;    // m col

    float acc[8][8];
    #pragma unroll
    for (int i = 0; i < 8; i++)
        #pragma unroll
        for (int j = 0; j < 8; j++) acc[i][j] = 0.f;

    float cmv[8];
    *(float4*)&cmv[0] = *(const float4*)(cm + m0 + cS);
    *(float4*)&cmv[4] = *(const float4*)(cm + m0 + cS + 4);

    float cacc[8];
    #pragma unroll
    for (int i = 0; i < 8; i++) cacc[i] = 0.f;

    for (int n0 = 0; n0 < 2048; n0 += 16) {
        float cr[8], sv[8];
        *(float4*)&cr[0] = *(const float4*)(Cb + (size_t)rA * 2048 + n0 + kbA);
        *(float4*)&cr[4] = *(const float4*)(Cb + (size_t)rA * 2048 + n0 + kbA + 4);
        *(float4*)&sv[0] = *(const float4*)(Pb + (size_t)(n0 + kS) * 2048 + m0 + cS);
        *(float4*)&sv[4] = *(const float4*)(Pb + (size_t)(n0 + kS) * 2048 + m0 + cS + 4);
        #pragma unroll
        for (int i = 0; i < 8; i++) {
            sv[i] = __expf(sv[i] - cmv[i]);
            cacc[i] += sv[i];
        }
        if (n0) __syncthreads();
        #pragma unroll
        for (int i = 0; i < 8; i++) Cs[kbA + i][rA] = cr[i];
        *(float4*)&Ss[kS][cS]     = make_float4(sv[0], sv[1], sv[2], sv[3]);
        *(float4*)&Ss[kS][cS + 4] = make_float4(sv[4], sv[5], sv[6], sv[7]);
        __syncthreads();
        #pragma unroll
        for (int k = 0; k < 16; k++) {
            float a[8], bb[8];
            *(float4*)&a[0]  = *(const float4*)&Cs[k][ty * 8];
            *(float4*)&a[4]  = *(const float4*)&Cs[k][ty * 8 + 4];
            *(float4*)&bb[0] = *(const float4*)&Ss[k][tx * 8];
            *(float4*)&bb[4] = *(const float4*)&Ss[k][tx * 8 + 4];
            #pragma unroll
            for (int i = 0; i < 8; i++)
                #pragma unroll
                for (int j = 0; j < 8; j++)
                    acc[i][j] += a[i] * bb[j];
        }
    }

    // column sums: reduce the 16 kS-stripe partials per column
    #pragma unroll
    for (int i = 0; i < 8; i++) csum[kS][cS + i] = cacc[i];
    __syncthreads();
    if (tid < 128) {
        float s = 0.f;
        #pragma unroll
        for (int g = 0; g < 16; g++) s += csum[g][tid];
        cinvs[tid] = 1.f / s;
    }
    __syncthreads();

    float ci[8];
    #pragma unroll
    for (int j = 0; j < 8; j++) ci[j] = cinvs[tx * 8 + j];

    #pragma unroll
    for (int i = 0; i < 8; i++) {
        float* dst = g_V + ((size_t)b * 128 + ty * 8 + i) * 2048 + m0 + tx * 8;
        *(float4*)dst       = make_float4(acc[i][0] * ci[0], acc[i][1] * ci[1],
                                          acc[i][2] * ci[2], acc[i][3] * ci[3]);
        *(float4*)(dst + 4) = make_float4(acc[i][4] * ci[4], acc[i][5] * ci[5],
                                          acc[i][6] * ci[6], acc[i][7] * ci[7]);
    }
}

// ---------------- assembly + JAX threefry dropout (partitionable layout) -----
__device__ __forceinline__ uint32_t threefry_mask_bits(uint32_t j)
{
    uint32_t x0 = 0u, x1 = j;
    const uint32_t k0 = 0u, k1 = 42u, k2 = 0x1BD11BDAu ^ 42u;
    x0 += k0; x1 += k1;
#define TF_ROUND(r) { x0 += x1; x1 = (x1 << (r)) | (x1 >> (32 - (r))); x1 ^= x0; }
    TF_ROUND(13) TF_ROUND(15) TF_ROUND(26) TF_ROUND(6)
    x0 += k1; x1 += k2 + 1u;
    TF_ROUND(17) TF_ROUND(29) TF_ROUND(16) TF_ROUND(24)
    x0 += k2; x1 += k0 + 2u;
    TF_ROUND(13) TF_ROUND(15) TF_ROUND(26) TF_ROUND(6)
    x0 += k0; x1 += k1 + 3u;
    TF_ROUND(17) TF_ROUND(29) TF_ROUND(16) TF_ROUND(24)
    x0 += k1; x1 += k2 + 4u;
    TF_ROUND(13) TF_ROUND(15) TF_ROUND(26) TF_ROUND(6)
    x0 += k2; x1 += k0 + 5u;
#undef TF_ROUND
    return x0 ^ x1;
}

__device__ __forceinline__ float fetch_val(uint32_t idx, const float* __restrict__ C)
{
    const int n = (int)(idx & 2047);
    const uint32_t t = idx >> 11;
    const int ch = (int)(t & 511);
    const int b = (int)(t >> 9);
    const int g = ch >> 7;
    const int d = ch & 127;
    const size_t off = (((size_t)b * 128 + d) << 11) + (size_t)n;
    if (g == 0) return C[off];
    if (g == 1) return g_A[off];
    if (g == 2) return C[off] * g_A[off];
    return C[off] * g_Bt[off];
}

__global__ __launch_bounds__(256) void assemble_kernel(const float* __restrict__ C,
                                                       float* __restrict__ out)
{
    const uint32_t j0 = (blockIdx.x * 256u + threadIdx.x) * 4u;
    float4 r;
    #pragma unroll
    for (int i = 0; i < 4; i++) {
        const uint32_t j = j0 + i;
        const uint32_t bits = threefry_mask_bits(j);
        const float u = __uint_as_float((bits >> 9) | 0x3f800000u) - 1.0f;
        const float v = (u < 0.9f) ? fetch_val(j, C) * (1.0f / 0.9f) : 0.f;
        (&r.x)[i] = v;
    }
    *(float4*)(out + j0) = r;
}

// ---------------- launch ----------------
extern "C" void kernel_launch(void* const* d_in, const int* in_sizes, int n_in,
                              void* d_out, int out_size)
{
    (void)in_sizes; (void)n_in; (void)out_size;
    const float* C = (const float*)d_in[0];
    const float* Q = (const float*)d_in[1];
    const float* W = (const float*)d_in[2];
    float* out = (float*)d_out;

    init_kernel<<<192, 256>>>();                   // rmax/cmax = -inf
    sqsc_kernel<<<dim3(8, 24, 2), 256>>>(C, Q, W);
    gemm1_kernel<<<dim3(16, 16, 24), 256>>>(C, Q, W);  // S + row/col maxes
    gemm_nt_kernel<0><<<dim3(16, 24), 256>>>(Q);   // A  = Q @ S1^T, writes g_rinv
    gemm_nn_kernel<<<dim3(16, 24), 256>>>(C);      // V  = C @ S2 (colsum in-block)
    gemm_nt_kernel<1><<<dim3(16, 24), 256>>>(Q);   // Bt = V @ S1^T, reads g_rinv
    assemble_kernel<<<TOTAL_OUT / (256 * 4), 256>>>(C, out);
}

// round 16
// speedup vs baseline: 1.0006x; 1.0006x over previous
#include <cuda_runtime.h>
#include <stdint.h>

// Problem constants: B=24, D=128, N=2048, M=2048
#define TOTAL_OUT 25165824u  // 24*512*2048

// ---------------- scratch (device globals; no allocations allowed) ----------------
__device__ float g_S  [(size_t)24 * 2048 * 2048];   // logits S[b][n][m]
__device__ float g_A  [(size_t)24 * 128 * 2048];    // A[b][d][n]
__device__ float g_V  [(size_t)24 * 128 * 2048];    // V[b][d][m] = C @ S2
__device__ float g_Bt [(size_t)24 * 128 * 2048];    // Bt[b][d][k] = V @ S1^T
__device__ float g_sq [24 * 2048];
__device__ float g_sc [24 * 2048];
__device__ float g_rmax[24 * 2048];                 // per-row max of S
__device__ float g_rinv[24 * 2048];                 // 1 / rowsum(exp(S - rmax))
__device__ float g_cmax[24 * 2048];                 // per-col max of S

// ---------------- float atomic max (mixed-sign safe, order-independent) ----------------
__device__ __forceinline__ void atomicMaxF(float* a, float v)
{
    if (v >= 0.f) atomicMax((int*)a, __float_as_int(v));
    else          atomicMin((unsigned int*)a, __float_as_uint(v));
}

// ---------------- init: rmax/cmax = -inf ----------------
__global__ __launch_bounds__(256) void init_kernel()
{
    const int i = blockIdx.x * 256 + threadIdx.x;   // i < 49152
    g_rmax[i] = __int_as_float(0xff800000);
    g_cmax[i] = __int_as_float(0xff800000);
}

// ---------------- sq / sc ----------------
__global__ __launch_bounds__(256) void sqsc_kernel(const float* __restrict__ C,
                                                   const float* __restrict__ Q,
                                                   const float* __restrict__ W)
{
    const int b = blockIdx.y;
    const int which = blockIdx.z;     // 0 -> sq (Wq . Q), 1 -> sc (Wc . C)
    const float* X = which ? C : Q;
    const float* w = W + b * 384 + (which ? 128 : 0);
    __shared__ float ws[128];
    if (threadIdx.x < 128) ws[threadIdx.x] = w[threadIdx.x];
    __syncthreads();
    const int m = blockIdx.x * 256 + threadIdx.x;
    const float* Xp = X + (size_t)b * 128 * 2048 + m;
    float acc = 0.f;
    #pragma unroll 8
    for (int d = 0; d < 128; d++)
        acc += ws[d] * Xp[(size_t)d * 2048];
    (which ? g_sc : g_sq)[b * 2048 + m] = acc;
}

// ---------------- GEMM1: S[n][m] = sum_d (C[d][n]*Wm[d]) * Q[d][m] + sc[n] + sq[m] -----
// Epilogue also reduces per-row and per-column tile maxes -> atomicMaxF into g_rmax/g_cmax.
__global__ __launch_bounds__(256) void gemm1_kernel(const float* __restrict__ C,
                                                    const float* __restrict__ Q,
                                                    const float* __restrict__ W)
{
    const int b  = blockIdx.z;
    const int n0 = blockIdx.y * 128;
    const int m0 = blockIdx.x * 128;
    const float* Cb = C + (size_t)b * 128 * 2048;
    const float* Qb = Q + (size_t)b * 128 * 2048;
    const float* Wm = W + b * 384 + 256;

    __shared__ float As[16][128];
    __shared__ float Bs[16][128];
    __shared__ float cms[16][136];

    const int tid = threadIdx.x;
    const int tx = tid & 15;          // m dir
    const int ty = tid >> 4;          // n dir
    const int lk = tid >> 4;          // load row in k-tile (0..15)
    const int lc = (tid & 15) * 8;    // load col (0..120)

    float acc[8][8];
    #pragma unroll
    for (int i = 0; i < 8; i++)
        #pragma unroll
        for (int j = 0; j < 8; j++) acc[i][j] = 0.f;

    for (int d0 = 0; d0 < 128; d0 += 16) {
        const float w = Wm[d0 + lk];
        const float4 c0 = *(const float4*)(Cb + (size_t)(d0 + lk) * 2048 + n0 + lc);
        const float4 c1 = *(const float4*)(Cb + (size_t)(d0 + lk) * 2048 + n0 + lc + 4);
        const float4 q0 = *(const float4*)(Qb + (size_t)(d0 + lk) * 2048 + m0 + lc);
        const float4 q1 = *(const float4*)(Qb + (size_t)(d0 + lk) * 2048 + m0 + lc + 4);
        if (d0) __syncthreads();
        *(float4*)&As[lk][lc]     = make_float4(c0.x * w, c0.y * w, c0.z * w, c0.w * w);
        *(float4*)&As[lk][lc + 4] = make_float4(c1.x * w, c1.y * w, c1.z * w, c1.w * w);
        *(float4*)&Bs[lk][lc]     = q0;
        *(float4*)&Bs[lk][lc + 4] = q1;
        __syncthreads();
        #pragma unroll
        for (int k = 0; k < 16; k++) {
            float a[8], bb[8];
            *(float4*)&a[0]  = *(const float4*)&As[k][ty * 8];
            *(float4*)&a[4]  = *(const float4*)&As[k][ty * 8 + 4];
            *(float4*)&bb[0] = *(const float4*)&Bs[k][tx * 8];
            *(float4*)&bb[4] = *(const float4*)&Bs[k][tx * 8 + 4];
            #pragma unroll
            for (int i = 0; i < 8; i++)
                #pragma unroll
                for (int j = 0; j < 8; j++)
                    acc[i][j] += a[i] * bb[j];
        }
    }

    const float* scp = g_sc + b * 2048 + n0 + ty * 8;
    const float* sqp = g_sq + b * 2048 + m0 + tx * 8;
    float sqv[8];
    #pragma unroll
    for (int j = 0; j < 8; j++) sqv[j] = sqp[j];

    float colm[8];
    #pragma unroll
    for (int j = 0; j < 8; j++) colm[j] = -1e30f;

    #pragma unroll
    for (int i = 0; i < 8; i++) {
        const float scv = scp[i];
        float v[8];
        float rowm = -1e30f;
        #pragma unroll
        for (int j = 0; j < 8; j++) {
            v[j] = acc[i][j] + scv + sqv[j];
            rowm = fmaxf(rowm, v[j]);
            colm[j] = fmaxf(colm[j], v[j]);
        }
        float* dst = g_S + ((size_t)b * 2048 + n0 + ty * 8 + i) * 2048 + m0 + tx * 8;
        *(float4*)dst       = make_float4(v[0], v[1], v[2], v[3]);
        *(float4*)(dst + 4) = make_float4(v[4], v[5], v[6], v[7]);
        // reduce row max over the 16 tx lanes (same half-warp)
        #pragma unroll
        for (int o = 1; o < 16; o <<= 1)
            rowm = fmaxf(rowm, __shfl_xor_sync(0xffffffffu, rowm, o));
        if (tx == 0) atomicMaxF(&g_rmax[b * 2048 + n0 + ty * 8 + i], rowm);
    }
    // column maxes: reduce over the 16 ty groups via shared
    #pragma unroll
    for (int j = 0; j < 8; j++) cms[ty][tx * 8 + j] = colm[j];
    __syncthreads();
    if (tid < 128) {
        float m = -1e30f;
        #pragma unroll
        for (int g = 0; g < 16; g++) m = fmaxf(m, cms[g][tid]);
        atomicMaxF(&g_cmax[b * 2048 + m0 + tid], m);
    }
}

// ---------------- NT GEMM: Out[b][d][j] = rinv[j] * sum_k X[b][d][k] * exp(S[j][k]-rmax[j])
// MODE 0: X = Q,   Out = A;  computes rowsum in-block, writes g_rinv.
// MODE 1: X = g_V, Out = Bt; reads g_rinv.
template<int MODE>
__global__ __launch_bounds__(256) void gemm_nt_kernel(const float* __restrict__ Xin)
{
    const int b  = blockIdx.y;
    const int j0 = blockIdx.x * 128;
    const float* X   = (MODE == 0) ? Xin : g_V;
    float* Out       = (MODE == 0) ? g_A : g_Bt;

    const float* Xb  = X + (size_t)b * 128 * 2048;
    const float* Sb  = g_S + (size_t)b * 2048 * 2048;

    __shared__ float Xs[16][132];
    __shared__ float Ss[16][132];
    __shared__ float rsum[128];

    const int tid = threadIdx.x;
    const int tx = tid & 15;
    const int ty = tid >> 4;
    const int r  = tid >> 1;           // 0..127  (row j0+r)
    const int kb = (tid & 1) * 8;      // 0 or 8

    float acc[8][8];
    #pragma unroll
    for (int i = 0; i < 8; i++)
        #pragma unroll
        for (int j = 0; j < 8; j++) acc[i][j] = 0.f;

    const float rm = g_rmax[b * 2048 + j0 + r];
    float racc = 0.f;

    for (int k0 = 0; k0 < 2048; k0 += 16) {
        float xr[8], sr[8];
        *(float4*)&xr[0] = *(const float4*)(Xb + (size_t)r * 2048 + k0 + kb);
        *(float4*)&xr[4] = *(const float4*)(Xb + (size_t)r * 2048 + k0 + kb + 4);
        *(float4*)&sr[0] = *(const float4*)(Sb + (size_t)(j0 + r) * 2048 + k0 + kb);
        *(float4*)&sr[4] = *(const float4*)(Sb + (size_t)(j0 + r) * 2048 + k0 + kb + 4);
        #pragma unroll
        for (int i = 0; i < 8; i++) {
            sr[i] = __expf(sr[i] - rm);      // in (0,1], never overflows/underflows row-wise
            if (MODE == 0) racc += sr[i];
        }
        if (k0) __syncthreads();
        #pragma unroll
        for (int i = 0; i < 8; i++) { Xs[kb + i][r] = xr[i]; Ss[kb + i][r] = sr[i]; }
        __syncthreads();
        #pragma unroll
        for (int k = 0; k < 16; k++) {
            float a[8], bb[8];
            *(float4*)&a[0]  = *(const float4*)&Xs[k][ty * 8];
            *(float4*)&a[4]  = *(const float4*)&Xs[k][ty * 8 + 4];
            *(float4*)&bb[0] = *(const float4*)&Ss[k][tx * 8];
            *(float4*)&bb[4] = *(const float4*)&Ss[k][tx * 8 + 4];
            #pragma unroll
            for (int i = 0; i < 8; i++)
                #pragma unroll
                for (int j = 0; j < 8; j++)
                    acc[i][j] += a[i] * bb[j];
        }
    }

    // rinv for this block's 128 j-columns (rowsum >= 1, always safe)
    if (MODE == 0) {
        racc += __shfl_xor_sync(0xffffffffu, racc, 1);  // merge kb=0 / kb=8 halves
        if ((tid & 1) == 0) rsum[r] = 1.f / racc;
        __syncthreads();
        if (tid < 128) g_rinv[b * 2048 + j0 + tid] = rsum[tid];
    } else {
        if (tid < 128) rsum[tid] = g_rinv[b * 2048 + j0 + tid];
        __syncthreads();
    }

    float ri[8];
    #pragma unroll
    for (int j = 0; j < 8; j++) ri[j] = rsum[tx * 8 + j];

    #pragma unroll
    for (int i = 0; i < 8; i++) {
        float* dst = Out + ((size_t)b * 128 + ty * 8 + i) * 2048 + j0 + tx * 8;
        *(float4*)dst       = make_float4(acc[i][0] * ri[0], acc[i][1] * ri[1],
                                          acc[i][2] * ri[2], acc[i][3] * ri[3]);
        *(float4*)(dst + 4) = make_float4(acc[i][4] * ri[4], acc[i][5] * ri[5],
                                          acc[i][6] * ri[6], acc[i][7] * ri[7]);
    }
}

// ---------------- NN GEMM: V[b][d][m] = cinv[m] * sum_n C[b][d][n] * exp(S[n][m]-cmax[m])
// colsum computed in-block (>= 1, always safe).
__global__ __launch_bounds__(256) void gemm_nn_kernel(const float* __restrict__ Cin)
{
    const int b  = blockIdx.y;
    const int m0 = blockIdx.x * 128;
    const float* Cb = Cin + (size_t)b * 128 * 2048;
    const float* Pb = g_S + (size_t)b * 2048 * 2048;
    const float* cm = g_cmax + b * 2048;

    __shared__ float Cs[16][132];
    __shared__ float Ss[16][132];
    __shared__ float csum[16][136];
    __shared__ float cinvs[128];

    const int tid = threadIdx.x;
    const int tx = tid & 15;
    const int ty = tid >> 4;
    const int rA  = tid >> 1;          // d row for C tile
    const int kbA = (tid & 1) * 8;     // n offset in tile
    const int kS  = tid >> 4;          // n row for S tile (0..15)
    const int cS  = (tid & 15) * 8;    // m col

    float acc[8][8];
    #pragma unroll
    for (int i = 0; i < 8; i++)
        #pragma unroll
        for (int j = 0; j < 8; j++) acc[i][j] = 0.f;

    float cmv[8];
    *(float4*)&cmv[0] = *(const float4*)(cm + m0 + cS);
    *(float4*)&cmv[4] = *(const float4*)(cm + m0 + cS + 4);

    float cacc[8];
    #pragma unroll
    for (int i = 0; i < 8; i++) cacc[i] = 0.f;

    for (int n0 = 0; n0 < 2048; n0 += 16) {
        float cr[8], sv[8];
        *(float4*)&cr[0] = *(const float4*)(Cb + (size_t)rA * 2048 + n0 + kbA);
        *(float4*)&cr[4] = *(const float4*)(Cb + (size_t)rA * 2048 + n0 + kbA + 4);
        *(float4*)&sv[0] = *(const float4*)(Pb + (size_t)(n0 + kS) * 2048 + m0 + cS);
        *(float4*)&sv[4] = *(const float4*)(Pb + (size_t)(n0 + kS) * 2048 + m0 + cS + 4);
        #pragma unroll
        for (int i = 0; i < 8; i++) {
            sv[i] = __expf(sv[i] - cmv[i]);
            cacc[i] += sv[i];
        }
        if (n0) __syncthreads();
        #pragma unroll
        for (int i = 0; i < 8; i++) Cs[kbA + i][rA] = cr[i];
        *(float4*)&Ss[kS][cS]     = make_float4(sv[0], sv[1], sv[2], sv[3]);
        *(float4*)&Ss[kS][cS + 4] = make_float4(sv[4], sv[5], sv[6], sv[7]);
        __syncthreads();
        #pragma unroll
        for (int k = 0; k < 16; k++) {
            float a[8], bb[8];
            *(float4*)&a[0]  = *(const float4*)&Cs[k][ty * 8];
            *(float4*)&a[4]  = *(const float4*)&Cs[k][ty * 8 + 4];
            *(float4*)&bb[0] = *(const float4*)&Ss[k][tx * 8];
            *(float4*)&bb[4] = *(const float4*)&Ss[k][tx * 8 + 4];
            #pragma unroll
            for (int i = 0; i < 8; i++)
                #pragma unroll
                for (int j = 0; j < 8; j++)
                    acc[i][j] += a[i] * bb[j];
        }
    }

    // column sums: reduce the 16 kS-stripe partials per column
    #pragma unroll
    for (int i = 0; i < 8; i++) csum[kS][cS + i] = cacc[i];
    __syncthreads();
    if (tid < 128) {
        float s = 0.f;
        #pragma unroll
        for (int g = 0; g < 16; g++) s += csum[g][tid];
        cinvs[tid] = 1.f / s;
    }
    __syncthreads();

    float ci[8];
    #pragma unroll
    for (int j = 0; j < 8; j++) ci[j] = cinvs[tx * 8 + j];

    #pragma unroll
    for (int i = 0; i < 8; i++) {
        float* dst = g_V + ((size_t)b * 128 + ty * 8 + i) * 2048 + m0 + tx * 8;
        *(float4*)dst       = make_float4(acc[i][0] * ci[0], acc[i][1] * ci[1],
                                          acc[i][2] * ci[2], acc[i][3] * ci[3]);
        *(float4*)(dst + 4) = make_float4(acc[i][4] * ci[4], acc[i][5] * ci[5],
                                          acc[i][6] * ci[6], acc[i][7] * ci[7]);
    }
}

// ---------------- assembly + JAX threefry dropout (partitionable layout) -----
__device__ __forceinline__ uint32_t threefry_mask_bits(uint32_t j)
{
    uint32_t x0 = 0u, x1 = j;
    const uint32_t k0 = 0u, k1 = 42u, k2 = 0x1BD11BDAu ^ 42u;
    x0 += k0; x1 += k1;
#define TF_ROUND(r) { x0 += x1; x1 = (x1 << (r)) | (x1 >> (32 - (r))); x1 ^= x0; }
    TF_ROUND(13) TF_ROUND(15) TF_ROUND(26) TF_ROUND(6)
    x0 += k1; x1 += k2 + 1u;
    TF_ROUND(17) TF_ROUND(29) TF_ROUND(16) TF_ROUND(24)
    x0 += k2; x1 += k0 + 2u;
    TF_ROUND(13) TF_ROUND(15) TF_ROUND(26) TF_ROUND(6)
    x0 += k0; x1 += k1 + 3u;
    TF_ROUND(17) TF_ROUND(29) TF_ROUND(16) TF_ROUND(24)
    x0 += k1; x1 += k2 + 4u;
    TF_ROUND(13) TF_ROUND(15) TF_ROUND(26) TF_ROUND(6)
    x0 += k2; x1 += k0 + 5u;
#undef TF_ROUND
    return x0 ^ x1;
}

__device__ __forceinline__ float fetch_val(uint32_t idx, const float* __restrict__ C)
{
    const int n = (int)(idx & 2047);
    const uint32_t t = idx >> 11;
    const int ch = (int)(t & 511);
    const int b = (int)(t >> 9);
    const int g = ch >> 7;
    const int d = ch & 127;
    const size_t off = (((size_t)b * 128 + d) << 11) + (size_t)n;
    if (g == 0) return C[off];
    if (g == 1) return g_A[off];
    if (g == 2) return C[off] * g_A[off];
    return C[off] * g_Bt[off];
}

__global__ __launch_bounds__(256) void assemble_kernel(const float* __restrict__ C,
                                                       float* __restrict__ out)
{
    const uint32_t j0 = (blockIdx.x * 256u + threadIdx.x) * 4u;
    float4 r;
    #pragma unroll
    for (int i = 0; i < 4; i++) {
        const uint32_t j = j0 + i;
        const uint32_t bits = threefry_mask_bits(j);
        const float u = __uint_as_float((bits >> 9) | 0x3f800000u) - 1.0f;
        const float v = (u < 0.9f) ? fetch_val(j, C) * (1.0f / 0.9f) : 0.f;
        (&r.x)[i] = v;
    }
    *(float4*)(out + j0) = r;
}

// ---------------- launch ----------------
extern "C" void kernel_launch(void* const* d_in, const int* in_sizes, int n_in,
                              void* d_out, int out_size)
{
    (void)in_sizes; (void)n_in; (void)out_size;
    const float* C = (const float*)d_in[0];
    const float* Q = (const float*)d_in[1];
    const float* W = (const float*)d_in[2];
    float* out = (float*)d_out;

    init_kernel<<<192, 256>>>();                   // rmax/cmax = -inf
    sqsc_kernel<<<dim3(8, 24, 2), 256>>>(C, Q, W);
    gemm1_kernel<<<dim3(16, 16, 24), 256>>>(C, Q, W);  // S + row/col maxes
    gemm_nt_kernel<0><<<dim3(16, 24), 256>>>(Q);   // A  = Q @ S1^T, writes g_rinv
    gemm_nn_kernel<<<dim3(16, 24), 256>>>(C);      // V  = C @ S2 (colsum in-block)
    gemm_nt_kernel<1><<<dim3(16, 24), 256>>>(Q);   // Bt = V @ S1^T, reads g_rinv
    assemble_kernel<<<TOTAL_OUT / (256 * 4), 256>>>(C, out);
}